// round 13
// baseline (speedup 1.0000x reference)
#include <cuda_runtime.h>

// ---------------------------------------------------------------------------
// CrossWindowAttention3D: 3D shifted-window attention (Video-Swin style)
//   spatial 48^3, C=96, heads=4 (hd=24), window 6^3 (216 tokens), shift 3
// Round 13: GEMM = proven R5 shape (4co x 8vox, scalar-broadcast W,
//   conflict-free X) shrunk to GV=96 @ 288 thr -> 3 CTAs/SM, 27 warps.
//   Attention = R10 structure with forced load/compute interleave:
//   V-load -> QK -> K(j+1) prefetch -> exp -> AV per key.
// ---------------------------------------------------------------------------

#define VOX   110592            // 48*48*48
#define NC    96
#define NH    4
#define HD    24
#define NTOK  216               // 6*6*6
#define NWIN  512               // 8*8*8
#define LOG2E 1.4426950408889634f
#define MASKC (-100.0f * LOG2E)
#define GV    96                // GEMM vox tile
#define GT    288               // GEMM threads
#define WR    97                // W smem row stride (co-major rows)

// Scratch (device globals: allocation-free rule)
__device__ float g_q[NC * VOX];
__device__ float g_k[NC * VOX];
__device__ float g_v[NC * VOX];
__device__ float g_o[NC * VOX];
__device__ float g_biasT[NH * NTOK * NTOK];   // [head][key j][query i], *log2(e)

typedef unsigned long long u64;

__device__ __forceinline__ float ex2f(float x) {
    float r;
    asm("ex2.approx.ftz.f32 %0, %1;" : "=f"(r) : "f"(x));
    return r;
}
// packed f32x2 ops (sm_103a FFMA2/FADD2 — only reachable via PTX f32x2 forms)
__device__ __forceinline__ u64 fma2(u64 a, u64 b, u64 c) {
    u64 d;
    asm("fma.rn.f32x2 %0, %1, %2, %3;" : "=l"(d) : "l"(a), "l"(b), "l"(c));
    return d;
}
__device__ __forceinline__ u64 add2(u64 a, u64 b) {
    u64 d;
    asm("add.rn.f32x2 %0, %1, %2;" : "=l"(d) : "l"(a), "l"(b));
    return d;
}
__device__ __forceinline__ u64 splat2(float x) {
    u64 d;
    asm("mov.b64 %0, {%1, %1};" : "=l"(d) : "f"(x));
    return d;
}
__device__ __forceinline__ u64 pack2(float lo, float hi) {
    u64 d;
    asm("mov.b64 %0, {%1, %2};" : "=l"(d) : "f"(lo), "f"(hi));
    return d;
}
__device__ __forceinline__ float hadd2(u64 a) {
    float lo, hi;
    asm("mov.b64 {%0, %1}, %2;" : "=f"(lo), "=f"(hi) : "l"(a));
    return lo + hi;
}
__device__ __forceinline__ float2 unpack2(u64 a) {
    float lo, hi;
    asm("mov.b64 {%0, %1}, %2;" : "=f"(lo), "=f"(hi) : "l"(a));
    return make_float2(lo, hi);
}

// ---------------------------------------------------------------------------
// Relative-position bias table, transposed to [h][j][i], premultiplied log2e.
// ---------------------------------------------------------------------------
extern "C" __global__ void bias_prep(const float* __restrict__ rel_table)
{
    int j = blockIdx.x;      // key token
    int i = threadIdx.x;     // query token
    int iz = i / 36, iy = (i / 6) % 6, ix = i % 6;
    int jz = j / 36, jy = (j / 6) % 6, jx = j % 6;
    int idx = ((iz - jz + 5) * 11 + (iy - jy + 5)) * 11 + (ix - jx + 5);
#pragma unroll
    for (int h = 0; h < NH; h++)
        g_biasT[h * (NTOK * NTOK) + j * NTOK + i] = rel_table[idx * NH + h] * LOG2E;
}

// ---------------------------------------------------------------------------
// GEMM: Y[96][VOX] = (W[96x96] @ X[96][VOX] + bias) * outScale
// CTA: 96 cout x 96 vox, 288 threads, thread tile 4 cout x 8 vox.
// smem: xs[96][96] + ws co-major [96][97] = 74112 B -> 3 CTAs/SM, 27 warps.
// X reads: LDS.128, 16B lane stride (conflict-free). W reads: uniform scalar.
// ---------------------------------------------------------------------------
extern "C" __global__ void __launch_bounds__(GT, 3)
gemm_proj(const float* __restrict__ X, const float* __restrict__ Wm,
          const float* __restrict__ bias, float* __restrict__ Y, float outScale)
{
    extern __shared__ float smem[];
    float* xs = smem;            // [96][GV=96]
    float* ws = smem + 96 * GV;  // [co][k], row stride WR=97

    const int tid   = threadIdx.x;
    const int vbase = blockIdx.x * GV;

    // Stage X tile (coalesced float4): 96*96/4 = 2304 float4
    for (int i = tid; i < 96 * GV / 4; i += GT) {
        int row = i / (GV / 4);
        int c4  = i - row * (GV / 4);
        const float4* p = reinterpret_cast<const float4*>(X + row * VOX + vbase);
        reinterpret_cast<float4*>(xs)[row * (GV / 4) + c4] = p[c4];
    }
    // Stage W co-major (direct copy: coalesced LDG, conflict-free STS)
    for (int i = tid; i < 96 * 96; i += GT) {
        int co = i / 96;
        int k  = i - co * 96;
        ws[co * WR + k] = Wm[i];
    }
    __syncthreads();

    const int voxg  = tid % 12;        // 0..11 -> 16B lane stride, conflict-free
    const int coutg = tid / 12;        // 0..23
    const int c0  = coutg * 4;
    const int v0a = voxg * 4;
    const int v0b = v0a + 48;

    const float* wp0 = ws + (c0 + 0) * WR;
    const float* wp1 = ws + (c0 + 1) * WR;
    const float* wp2 = ws + (c0 + 2) * WR;
    const float* wp3 = ws + (c0 + 3) * WR;

    u64 acc[4][4];
#pragma unroll
    for (int u = 0; u < 4; u++)
#pragma unroll
        for (int p = 0; p < 4; p++) acc[u][p] = 0ULL;

#pragma unroll 4
    for (int k = 0; k < 96; k++) {
        ulonglong2 b0 = *reinterpret_cast<const ulonglong2*>(&xs[k * GV + v0a]);
        ulonglong2 b1 = *reinterpret_cast<const ulonglong2*>(&xs[k * GV + v0b]);
        u64 w0 = splat2(wp0[k]);
        u64 w1 = splat2(wp1[k]);
        u64 w2 = splat2(wp2[k]);
        u64 w3 = splat2(wp3[k]);
        acc[0][0] = fma2(w0, b0.x, acc[0][0]);
        acc[0][1] = fma2(w0, b0.y, acc[0][1]);
        acc[0][2] = fma2(w0, b1.x, acc[0][2]);
        acc[0][3] = fma2(w0, b1.y, acc[0][3]);
        acc[1][0] = fma2(w1, b0.x, acc[1][0]);
        acc[1][1] = fma2(w1, b0.y, acc[1][1]);
        acc[1][2] = fma2(w1, b1.x, acc[1][2]);
        acc[1][3] = fma2(w1, b1.y, acc[1][3]);
        acc[2][0] = fma2(w2, b0.x, acc[2][0]);
        acc[2][1] = fma2(w2, b0.y, acc[2][1]);
        acc[2][2] = fma2(w2, b1.x, acc[2][2]);
        acc[2][3] = fma2(w2, b1.y, acc[2][3]);
        acc[3][0] = fma2(w3, b0.x, acc[3][0]);
        acc[3][1] = fma2(w3, b0.y, acc[3][1]);
        acc[3][2] = fma2(w3, b1.x, acc[3][2]);
        acc[3][3] = fma2(w3, b1.y, acc[3][3]);
    }

#pragma unroll
    for (int u = 0; u < 4; u++) {
        float bb = bias[c0 + u];
        float2 p0 = unpack2(acc[u][0]);
        float2 p1 = unpack2(acc[u][1]);
        float2 p2 = unpack2(acc[u][2]);
        float2 p3 = unpack2(acc[u][3]);
        float4 r0 = make_float4((p0.x + bb) * outScale, (p0.y + bb) * outScale,
                                (p1.x + bb) * outScale, (p1.y + bb) * outScale);
        float4 r1 = make_float4((p2.x + bb) * outScale, (p2.y + bb) * outScale,
                                (p3.x + bb) * outScale, (p3.y + bb) * outScale);
        float* yp = Y + (c0 + u) * VOX + vbase;
        *reinterpret_cast<float4*>(yp + v0a) = r0;
        *reinterpret_cast<float4*>(yp + v0b) = r1;
    }
}

// ---------------------------------------------------------------------------
// Attention: one CTA per (window, head), 128 threads; threads 0..107 own TWO
// query rows (tid, tid+108). Per key: V-load -> QK FMAs -> K(j+1) prefetch ->
// exp -> AV FMAs, so each LDS result sits behind ~48 issue-cycles of
// independent FMA (covers the 29-cyc LDS latency; overlaps load & compute).
// Max-free softmax in exp2 domain (logits bounded; validated since round 4).
// ---------------------------------------------------------------------------
extern "C" __global__ void __launch_bounds__(128, 3)
attn_kernel(const int* __restrict__ use_shift)
{
    __shared__ __align__(16) float ks[NTOK * HD];
    __shared__ __align__(16) float vs[NTOK * HD];
    __shared__ int voxof[NTOK];
    __shared__ int rcode[NTOK];

    const int win  = blockIdx.x >> 2;
    const int head = blockIdx.x & 3;
    const int tid  = threadIdx.x;
    const bool sh  = (use_shift[0] != 0);
    const int shift = sh ? 3 : 0;
    const int wx = win & 7, wy = (win >> 3) & 7, wz = win >> 6;
    const bool needmask = sh && (wx == 7 || wy == 7 || wz == 7);

    for (int t = tid; t < NTOK; t += 128) {
        int tz = t / 36, ty = (t / 6) % 6, tx = t % 6;
        int gz = wz * 6 + tz, gy = wy * 6 + ty, gx = wx * 6 + tx;
        int sz = gz + shift; if (sz >= 48) sz -= 48;
        int sy = gy + shift; if (sy >= 48) sy -= 48;
        int sx = gx + shift; if (sx >= 48) sx -= 48;
        voxof[t] = (sz * 48 + sy) * 48 + sx;
        int rz = gz < 42 ? 0 : (gz < 45 ? 1 : 2);
        int ry = gy < 42 ? 0 : (gy < 45 ? 1 : 2);
        int rx = gx < 42 ? 0 : (gx < 45 ? 1 : 2);
        rcode[t] = rz * 9 + ry * 3 + rx;
    }
    __syncthreads();

    // Stage K and V tiles (coalesced 24B runs in gmem)
    const float* kb = g_k + head * HD * VOX;
    const float* vb = g_v + head * HD * VOX;
    for (int idx = tid; idx < NTOK * HD; idx += 128) {
        int dch = idx / NTOK;
        int j   = idx - dch * NTOK;
        int vx  = voxof[j];
        ks[j * HD + dch] = kb[dch * VOX + vx];
        vs[j * HD + dch] = vb[dch * VOX + vx];
    }

    u64 qa[12], qb[12], oa[12], ob[12];
    float la = 0.f, lb = 0.f;
    int voxA = 0, voxB = 0, rA = 0, rB = 0;
    if (tid < 108) {
        voxA = voxof[tid];       rA = rcode[tid];
        voxB = voxof[tid + 108]; rB = rcode[tid + 108];
        const float* qpA = g_q + head * HD * VOX + voxA;
        const float* qpB = g_q + head * HD * VOX + voxB;
#pragma unroll
        for (int d = 0; d < 12; d++) {
            qa[d] = pack2(qpA[(2 * d) * VOX], qpA[(2 * d + 1) * VOX]);
            qb[d] = pack2(qpB[(2 * d) * VOX], qpB[(2 * d + 1) * VOX]);
        }
    }
#pragma unroll
    for (int d = 0; d < 12; d++) { oa[d] = 0ULL; ob[d] = 0ULL; }
    __syncthreads();

    if (tid < 108) {
        const float* biasA = g_biasT + head * (NTOK * NTOK) + tid;
        const float* biasB = biasA + 108;

        // current-key K buffer (prefetched one key ahead)
        ulonglong2 kc0, kc1, kc2, kc3, kc4, kc5;
        {
            const ulonglong2* kr = reinterpret_cast<const ulonglong2*>(&ks[0]);
            kc0 = kr[0]; kc1 = kr[1]; kc2 = kr[2];
            kc3 = kr[3]; kc4 = kr[4]; kc5 = kr[5];
        }

        for (int jb = 0; jb < NTOK; jb += 8) {
            float sA[8], sB[8];
#pragma unroll
            for (int g = 0; g < 8; g++) {
                sA[g] = biasA[(jb + g) * NTOK];
                sB[g] = biasB[(jb + g) * NTOK];
            }
            if (needmask) {
#pragma unroll
                for (int g = 0; g < 8; g++) {
                    int rc = rcode[jb + g];
                    if (rc != rA) sA[g] += MASKC;
                    if (rc != rB) sB[g] += MASKC;
                }
            }
#pragma unroll
            for (int g = 0; g < 8; g++) {
                int j = jb + g;
                // 1) V load (consumed only after QK + exp: ~60 cyc later)
                const ulonglong2* vr = reinterpret_cast<const ulonglong2*>(&vs[j * HD]);
                ulonglong2 v0 = vr[0], v1 = vr[1], v2 = vr[2];
                ulonglong2 v3 = vr[3], v4 = vr[4], v5 = vr[5];

                // 2) QK with current K buffer
                u64 aA0 = fma2(qa[0], kc0.x, 0ULL);
                u64 aA1 = fma2(qa[1], kc0.y, 0ULL);
                u64 aB0 = fma2(qb[0], kc0.x, 0ULL);
                u64 aB1 = fma2(qb[1], kc0.y, 0ULL);
                aA0 = fma2(qa[2], kc1.x, aA0);  aA1 = fma2(qa[3], kc1.y, aA1);
                aB0 = fma2(qb[2], kc1.x, aB0);  aB1 = fma2(qb[3], kc1.y, aB1);
                aA0 = fma2(qa[4], kc2.x, aA0);  aA1 = fma2(qa[5], kc2.y, aA1);
                aB0 = fma2(qb[4], kc2.x, aB0);  aB1 = fma2(qb[5], kc2.y, aB1);
                aA0 = fma2(qa[6], kc3.x, aA0);  aA1 = fma2(qa[7], kc3.y, aA1);
                aB0 = fma2(qb[6], kc3.x, aB0);  aB1 = fma2(qb[7], kc3.y, aB1);
                aA0 = fma2(qa[8], kc4.x, aA0);  aA1 = fma2(qa[9], kc4.y, aA1);
                aB0 = fma2(qb[8], kc4.x, aB0);  aB1 = fma2(qb[9], kc4.y, aB1);
                aA0 = fma2(qa[10], kc5.x, aA0); aA1 = fma2(qa[11], kc5.y, aA1);
                aB0 = fma2(qb[10], kc5.x, aB0); aB1 = fma2(qb[11], kc5.y, aB1);

                // 3) prefetch next key's K (used after exp + AV: ~60 cyc later)
                {
                    int jn = (j + 1 < NTOK) ? (j + 1) : 0;   // wrap load, unused
                    const ulonglong2* krn = reinterpret_cast<const ulonglong2*>(&ks[jn * HD]);
                    kc0 = krn[0]; kc1 = krn[1]; kc2 = krn[2];
                    kc3 = krn[3]; kc4 = krn[4]; kc5 = krn[5];
                }

                // 4) exp + accumulate l
                float pA = ex2f(sA[g] + hadd2(add2(aA0, aA1)));
                float pB = ex2f(sB[g] + hadd2(add2(aB0, aB1)));
                la += pA;
                lb += pB;
                u64 ppA = splat2(pA);
                u64 ppB = splat2(pB);

                // 5) AV with V loaded in step 1
                oa[0]  = fma2(ppA, v0.x, oa[0]);   ob[0]  = fma2(ppB, v0.x, ob[0]);
                oa[1]  = fma2(ppA, v0.y, oa[1]);   ob[1]  = fma2(ppB, v0.y, ob[1]);
                oa[2]  = fma2(ppA, v1.x, oa[2]);   ob[2]  = fma2(ppB, v1.x, ob[2]);
                oa[3]  = fma2(ppA, v1.y, oa[3]);   ob[3]  = fma2(ppB, v1.y, ob[3]);
                oa[4]  = fma2(ppA, v2.x, oa[4]);   ob[4]  = fma2(ppB, v2.x, ob[4]);
                oa[5]  = fma2(ppA, v2.y, oa[5]);   ob[5]  = fma2(ppB, v2.y, ob[5]);
                oa[6]  = fma2(ppA, v3.x, oa[6]);   ob[6]  = fma2(ppB, v3.x, ob[6]);
                oa[7]  = fma2(ppA, v3.y, oa[7]);   ob[7]  = fma2(ppB, v3.y, ob[7]);
                oa[8]  = fma2(ppA, v4.x, oa[8]);   ob[8]  = fma2(ppB, v4.x, ob[8]);
                oa[9]  = fma2(ppA, v4.y, oa[9]);   ob[9]  = fma2(ppB, v4.y, ob[9]);
                oa[10] = fma2(ppA, v5.x, oa[10]);  ob[10] = fma2(ppB, v5.x, ob[10]);
                oa[11] = fma2(ppA, v5.y, oa[11]);  ob[11] = fma2(ppB, v5.y, ob[11]);
            }
        }
        float invA = 1.0f / la;
        float invB = 1.0f / lb;
        float* opA = g_o + head * HD * VOX + voxA;
        float* opB = g_o + head * HD * VOX + voxB;
#pragma unroll
        for (int d = 0; d < 12; d++) {
            float2 va = unpack2(oa[d]);
            float2 vb2 = unpack2(ob[d]);
            opA[(2 * d) * VOX]     = va.x * invA;
            opA[(2 * d + 1) * VOX] = va.y * invA;
            opB[(2 * d) * VOX]     = vb2.x * invB;
            opB[(2 * d + 1) * VOX] = vb2.y * invB;
        }
    }
}

// ---------------------------------------------------------------------------
// kernel_launch
// inputs: 0:q_in 1:k_in 2:v_in 3:Wq 4:bq 5:Wk 6:bk 7:Wv 8:bv 9:Wp 10:bp
//         11:rel_table 12:use_shift
// ---------------------------------------------------------------------------
extern "C" void kernel_launch(void* const* d_in, const int* in_sizes, int n_in,
                              void* d_out, int out_size)
{
    const float* q_in = (const float*)d_in[0];
    const float* k_in = (const float*)d_in[1];
    const float* v_in = (const float*)d_in[2];
    const float* Wq   = (const float*)d_in[3];
    const float* bq   = (const float*)d_in[4];
    const float* Wk   = (const float*)d_in[5];
    const float* bk   = (const float*)d_in[6];
    const float* Wv   = (const float*)d_in[7];
    const float* bv   = (const float*)d_in[8];
    const float* Wp   = (const float*)d_in[9];
    const float* bp   = (const float*)d_in[10];
    const float* rel  = (const float*)d_in[11];
    const int*   ush  = (const int*)d_in[12];

    float *pq, *pk, *pv, *po;
    cudaGetSymbolAddress((void**)&pq, g_q);
    cudaGetSymbolAddress((void**)&pk, g_k);
    cudaGetSymbolAddress((void**)&pv, g_v);
    cudaGetSymbolAddress((void**)&po, g_o);

    const int SMEM_GEMM = (96 * GV + 96 * WR) * (int)sizeof(float);  // 74112
    cudaFuncSetAttribute(gemm_proj, cudaFuncAttributeMaxDynamicSharedMemorySize, SMEM_GEMM);

    const float scale_q = (1.0f / 4.898979485566356f) * LOG2E;  // 24^-0.5 * log2(e)

    bias_prep<<<NTOK, NTOK>>>(rel);
    gemm_proj<<<VOX / GV, GT, SMEM_GEMM>>>(q_in, Wq, bq, pq, scale_q);
    gemm_proj<<<VOX / GV, GT, SMEM_GEMM>>>(k_in, Wk, bk, pk, 1.0f);
    gemm_proj<<<VOX / GV, GT, SMEM_GEMM>>>(v_in, Wv, bv, pv, 1.0f);
    attn_kernel<<<NWIN * NH, 128>>>(ush);
    gemm_proj<<<VOX / GV, GT, SMEM_GEMM>>>(po, Wp, bp, (float*)d_out, 1.0f);
}

// round 14
// speedup vs baseline: 1.2738x; 1.2738x over previous
#include <cuda_runtime.h>
#include <cstdint>

// ---------------------------------------------------------------------------
// CrossWindowAttention3D: 3D shifted-window attention (Video-Swin style)
//   spatial 48^3, C=96, heads=4 (hd=24), window 6^3 (216 tokens), shift 3
// Round 14: scalar fp32 is AT the roofline (model + 9 rounds of evidence),
//   so the projections move to tensor cores: mma.sync m16n8k8 TF32, inputs
//   pre-converted to tf32 in smem, fp32 accumulate. Attention = R10 best.
// ---------------------------------------------------------------------------

#define VOX   110592            // 48*48*48
#define NC    96
#define NH    4
#define HD    24
#define NTOK  216               // 6*6*6
#define NWIN  512               // 8*8*8
#define LOG2E 1.4426950408889634f
#define MASKC (-100.0f * LOG2E)
#define XS_STRIDE 136           // xs row stride (floats): bank = 8*tig+gid, bijective
#define WS_STRIDE 100           // ws row stride (floats): bank = 4*gid+tig, bijective

// Scratch (device globals: allocation-free rule)
__device__ float g_q[NC * VOX];
__device__ float g_k[NC * VOX];
__device__ float g_v[NC * VOX];
__device__ float g_o[NC * VOX];
__device__ float g_biasT[NH * NTOK * NTOK];   // [head][key j][query i], *log2(e)

typedef unsigned long long u64;

__device__ __forceinline__ float ex2f(float x) {
    float r;
    asm("ex2.approx.ftz.f32 %0, %1;" : "=f"(r) : "f"(x));
    return r;
}
__device__ __forceinline__ u64 fma2(u64 a, u64 b, u64 c) {
    u64 d;
    asm("fma.rn.f32x2 %0, %1, %2, %3;" : "=l"(d) : "l"(a), "l"(b), "l"(c));
    return d;
}
__device__ __forceinline__ u64 add2(u64 a, u64 b) {
    u64 d;
    asm("add.rn.f32x2 %0, %1, %2;" : "=l"(d) : "l"(a), "l"(b));
    return d;
}
__device__ __forceinline__ u64 splat2(float x) {
    u64 d;
    asm("mov.b64 %0, {%1, %1};" : "=l"(d) : "f"(x));
    return d;
}
__device__ __forceinline__ u64 pack2(float lo, float hi) {
    u64 d;
    asm("mov.b64 %0, {%1, %2};" : "=l"(d) : "f"(lo), "f"(hi));
    return d;
}
__device__ __forceinline__ float hadd2(u64 a) {
    float lo, hi;
    asm("mov.b64 {%0, %1}, %2;" : "=f"(lo), "=f"(hi) : "l"(a));
    return lo + hi;
}
__device__ __forceinline__ float2 unpack2(u64 a) {
    float lo, hi;
    asm("mov.b64 {%0, %1}, %2;" : "=f"(lo), "=f"(hi) : "l"(a));
    return make_float2(lo, hi);
}
__device__ __forceinline__ uint32_t f2tf32(float f) {
    uint32_t u;
    asm("cvt.rna.tf32.f32 %0, %1;" : "=r"(u) : "f"(f));
    return u;
}
// mma.sync m16n8k8 tf32: D = A*B + C (fp32 accum)
__device__ __forceinline__ void mma_tf32(float c[4],
                                         const uint32_t a[4], const uint32_t b[2]) {
    asm volatile(
        "mma.sync.aligned.m16n8k8.row.col.f32.tf32.tf32.f32 "
        "{%0,%1,%2,%3}, {%4,%5,%6,%7}, {%8,%9}, {%0,%1,%2,%3};"
        : "+f"(c[0]), "+f"(c[1]), "+f"(c[2]), "+f"(c[3])
        : "r"(a[0]), "r"(a[1]), "r"(a[2]), "r"(a[3]), "r"(b[0]), "r"(b[1]));
}

// ---------------------------------------------------------------------------
// Relative-position bias table, transposed to [h][j][i], premultiplied log2e.
// ---------------------------------------------------------------------------
extern "C" __global__ void bias_prep(const float* __restrict__ rel_table)
{
    int j = blockIdx.x;      // key token
    int i = threadIdx.x;     // query token
    int iz = i / 36, iy = (i / 6) % 6, ix = i % 6;
    int jz = j / 36, jy = (j / 6) % 6, jx = j % 6;
    int idx = ((iz - jz + 5) * 11 + (iy - jy + 5)) * 11 + (ix - jx + 5);
#pragma unroll
    for (int h = 0; h < NH; h++)
        g_biasT[h * (NTOK * NTOK) + j * NTOK + i] = rel_table[idx * NH + h] * LOG2E;
}

// ---------------------------------------------------------------------------
// Projection GEMM on tensor cores (TF32 mma.sync):
//   Y[96][VOX] = (W[96x96] @ X[96][VOX] + bias) * outScale
// CTA: 96co x 128vox, 384 threads (12 warps, 3 m-warps x 4 n-warps),
// warp tile 32co x 32vox = 2 m-frags x 4 n-frags, K=96 in 12 k-steps.
// X staged as xs[k][vox] (stride 136), W as ws[co][k] (stride 100) — both
// pre-converted to tf32; all fragment LDS.32 are bank-conflict-free.
// Fragment maps (PTX m16n8k8 tf32): gid=lane>>2, tig=lane&3;
//   A: a0=(gid,tig) a1=(gid+8,tig) a2=(gid,tig+4) a3=(gid+8,tig+4)
//   B: b0=(k=tig,n=gid) b1=(k=tig+4,n=gid)
//   C: c0=(gid,2tig) c1=(gid,2tig+1) c2=(gid+8,2tig) c3=(gid+8,2tig+1)
// ---------------------------------------------------------------------------
extern "C" __global__ void __launch_bounds__(384, 2)
gemm_mma(const float* __restrict__ X, const float* __restrict__ Wm,
         const float* __restrict__ bias, float* __restrict__ Y, float outScale)
{
    extern __shared__ float smem[];
    float* xs = smem;                    // [96][XS_STRIDE] tf32 bits
    float* ws = smem + 96 * XS_STRIDE;   // [96][WS_STRIDE] tf32 bits

    const int tid   = threadIdx.x;
    const int vbase = blockIdx.x * 128;

    // Stage X (coalesced float4 LDG, convert to tf32, STS)
    for (int i = tid; i < 96 * 32; i += 384) {
        int row = i >> 5;
        int c4  = i & 31;
        float4 v = reinterpret_cast<const float4*>(X + row * VOX + vbase)[c4];
        uint4 t;
        t.x = f2tf32(v.x); t.y = f2tf32(v.y); t.z = f2tf32(v.z); t.w = f2tf32(v.w);
        *reinterpret_cast<uint4*>(&xs[row * XS_STRIDE + c4 * 4]) = t;
    }
    // Stage W (row co, 24 float4 per row)
    for (int i = tid; i < 96 * 24; i += 384) {
        int co = i / 24;
        int c4 = i - co * 24;
        float4 v = reinterpret_cast<const float4*>(Wm + co * 96)[c4];
        uint4 t;
        t.x = f2tf32(v.x); t.y = f2tf32(v.y); t.z = f2tf32(v.z); t.w = f2tf32(v.w);
        *reinterpret_cast<uint4*>(&ws[co * WS_STRIDE + c4 * 4]) = t;
    }
    __syncthreads();

    const int warp = tid >> 5;
    const int lane = tid & 31;
    const int gid  = lane >> 2;
    const int tig  = lane & 3;
    const int m0   = (warp % 3) * 32;    // cout base of this warp
    const int n0   = (warp / 3) * 32;    // vox  base of this warp

    const uint32_t* xsu = reinterpret_cast<const uint32_t*>(xs);
    const uint32_t* wsu = reinterpret_cast<const uint32_t*>(ws);

    float cf[2][4][4];
#pragma unroll
    for (int mf = 0; mf < 2; mf++)
#pragma unroll
        for (int nf = 0; nf < 4; nf++)
#pragma unroll
            for (int e = 0; e < 4; e++) cf[mf][nf][e] = 0.f;

#pragma unroll
    for (int ks = 0; ks < 12; ks++) {
        const int k0 = ks * 8;
        uint32_t a[2][4];
#pragma unroll
        for (int mf = 0; mf < 2; mf++) {
            int r = (m0 + mf * 16 + gid) * WS_STRIDE + k0 + tig;
            a[mf][0] = wsu[r];
            a[mf][1] = wsu[r + 8 * WS_STRIDE];
            a[mf][2] = wsu[r + 4];
            a[mf][3] = wsu[r + 8 * WS_STRIDE + 4];
        }
        uint32_t b[4][2];
#pragma unroll
        for (int nf = 0; nf < 4; nf++) {
            int c = (k0 + tig) * XS_STRIDE + n0 + nf * 8 + gid;
            b[nf][0] = xsu[c];
            b[nf][1] = xsu[c + 4 * XS_STRIDE];
        }
#pragma unroll
        for (int mf = 0; mf < 2; mf++)
#pragma unroll
            for (int nf = 0; nf < 4; nf++)
                mma_tf32(cf[mf][nf], a[mf], b[nf]);
    }

    // Epilogue: bias + scale, float2 stores (32B contiguous per 4 lanes)
#pragma unroll
    for (int mf = 0; mf < 2; mf++) {
        int r0 = m0 + mf * 16 + gid;
        int r1 = r0 + 8;
        float bb0 = bias[r0];
        float bb1 = bias[r1];
#pragma unroll
        for (int nf = 0; nf < 4; nf++) {
            int c = vbase + n0 + nf * 8 + 2 * tig;
            float2 s0 = make_float2((cf[mf][nf][0] + bb0) * outScale,
                                    (cf[mf][nf][1] + bb0) * outScale);
            float2 s1 = make_float2((cf[mf][nf][2] + bb1) * outScale,
                                    (cf[mf][nf][3] + bb1) * outScale);
            *reinterpret_cast<float2*>(&Y[r0 * VOX + c]) = s0;
            *reinterpret_cast<float2*>(&Y[r1 * VOX + c]) = s1;
        }
    }
}

// ---------------------------------------------------------------------------
// Attention (round-10 measured best): one CTA per (window, head), 128 threads;
// threads 0..107 each own TWO query rows (tid, tid+108). Max-free softmax in
// exp2 domain (logits bounded; validated since round 4).
// ---------------------------------------------------------------------------
extern "C" __global__ void __launch_bounds__(128, 3)
attn_kernel(const int* __restrict__ use_shift)
{
    __shared__ __align__(16) float ks[NTOK * HD];
    __shared__ __align__(16) float vs[NTOK * HD];
    __shared__ int voxof[NTOK];
    __shared__ int rcode[NTOK];

    const int win  = blockIdx.x >> 2;
    const int head = blockIdx.x & 3;
    const int tid  = threadIdx.x;
    const bool sh  = (use_shift[0] != 0);
    const int shift = sh ? 3 : 0;
    const int wx = win & 7, wy = (win >> 3) & 7, wz = win >> 6;
    const bool needmask = sh && (wx == 7 || wy == 7 || wz == 7);

    for (int t = tid; t < NTOK; t += 128) {
        int tz = t / 36, ty = (t / 6) % 6, tx = t % 6;
        int gz = wz * 6 + tz, gy = wy * 6 + ty, gx = wx * 6 + tx;
        int sz = gz + shift; if (sz >= 48) sz -= 48;
        int sy = gy + shift; if (sy >= 48) sy -= 48;
        int sx = gx + shift; if (sx >= 48) sx -= 48;
        voxof[t] = (sz * 48 + sy) * 48 + sx;
        int rz = gz < 42 ? 0 : (gz < 45 ? 1 : 2);
        int ry = gy < 42 ? 0 : (gy < 45 ? 1 : 2);
        int rx = gx < 42 ? 0 : (gx < 45 ? 1 : 2);
        rcode[t] = rz * 9 + ry * 3 + rx;
    }
    __syncthreads();

    // Stage K and V tiles (coalesced 24B runs in gmem)
    const float* kb = g_k + head * HD * VOX;
    const float* vb = g_v + head * HD * VOX;
    for (int idx = tid; idx < NTOK * HD; idx += 128) {
        int dch = idx / NTOK;
        int j   = idx - dch * NTOK;
        int vx  = voxof[j];
        ks[j * HD + dch] = kb[dch * VOX + vx];
        vs[j * HD + dch] = vb[dch * VOX + vx];
    }

    u64 qa[12], qb[12], oa[12], ob[12];
    float la0 = 0.f, la1 = 0.f, lb0 = 0.f, lb1 = 0.f;
    int voxA = 0, voxB = 0, rA = 0, rB = 0;
    if (tid < 108) {
        voxA = voxof[tid];       rA = rcode[tid];
        voxB = voxof[tid + 108]; rB = rcode[tid + 108];
        const float* qpA = g_q + head * HD * VOX + voxA;
        const float* qpB = g_q + head * HD * VOX + voxB;
#pragma unroll
        for (int d = 0; d < 12; d++) {
            qa[d] = pack2(qpA[(2 * d) * VOX], qpA[(2 * d + 1) * VOX]);
            qb[d] = pack2(qpB[(2 * d) * VOX], qpB[(2 * d + 1) * VOX]);
        }
    }
#pragma unroll
    for (int d = 0; d < 12; d++) { oa[d] = 0ULL; ob[d] = 0ULL; }
    __syncthreads();

    if (tid < 108) {
        const float* biasA = g_biasT + head * (NTOK * NTOK) + tid;
        const float* biasB = biasA + 108;
        for (int jb = 0; jb < NTOK; jb += 8) {
            float sA[8], sB[8];
#pragma unroll
            for (int g = 0; g < 8; g++) {
                sA[g] = biasA[(jb + g) * NTOK];
                sB[g] = biasB[(jb + g) * NTOK];
            }
            if (needmask) {
#pragma unroll
                for (int g = 0; g < 8; g++) {
                    int rc = rcode[jb + g];
                    if (rc != rA) sA[g] += MASKC;
                    if (rc != rB) sB[g] += MASKC;
                }
            }
#pragma unroll
            for (int g = 0; g < 8; g++) {
                int j = jb + g;
                const ulonglong2* kr = reinterpret_cast<const ulonglong2*>(&ks[j * HD]);
                ulonglong2 k0 = kr[0], k1 = kr[1], k2 = kr[2];
                ulonglong2 k3 = kr[3], k4 = kr[4], k5 = kr[5];

                u64 aA0 = fma2(qa[0], k0.x, 0ULL);
                u64 aA1 = fma2(qa[1], k0.y, 0ULL);
                u64 aB0 = fma2(qb[0], k0.x, 0ULL);
                u64 aB1 = fma2(qb[1], k0.y, 0ULL);
                aA0 = fma2(qa[2], k1.x, aA0);  aA1 = fma2(qa[3], k1.y, aA1);
                aB0 = fma2(qb[2], k1.x, aB0);  aB1 = fma2(qb[3], k1.y, aB1);
                aA0 = fma2(qa[4], k2.x, aA0);  aA1 = fma2(qa[5], k2.y, aA1);
                aB0 = fma2(qb[4], k2.x, aB0);  aB1 = fma2(qb[5], k2.y, aB1);
                aA0 = fma2(qa[6], k3.x, aA0);  aA1 = fma2(qa[7], k3.y, aA1);
                aB0 = fma2(qb[6], k3.x, aB0);  aB1 = fma2(qb[7], k3.y, aB1);
                aA0 = fma2(qa[8], k4.x, aA0);  aA1 = fma2(qa[9], k4.y, aA1);
                aB0 = fma2(qb[8], k4.x, aB0);  aB1 = fma2(qb[9], k4.y, aB1);
                aA0 = fma2(qa[10], k5.x, aA0); aA1 = fma2(qa[11], k5.y, aA1);
                aB0 = fma2(qb[10], k5.x, aB0); aB1 = fma2(qb[11], k5.y, aB1);

                float pA = ex2f(sA[g] + hadd2(add2(aA0, aA1)));
                float pB = ex2f(sB[g] + hadd2(add2(aB0, aB1)));
                if (g & 1) { la1 += pA; lb1 += pB; }
                else       { la0 += pA; lb0 += pB; }
                u64 ppA = splat2(pA);
                u64 ppB = splat2(pB);

                const ulonglong2* vr = reinterpret_cast<const ulonglong2*>(&vs[j * HD]);
                ulonglong2 v0 = vr[0], v1 = vr[1], v2 = vr[2];
                ulonglong2 v3 = vr[3], v4 = vr[4], v5 = vr[5];
                oa[0]  = fma2(ppA, v0.x, oa[0]);   ob[0]  = fma2(ppB, v0.x, ob[0]);
                oa[1]  = fma2(ppA, v0.y, oa[1]);   ob[1]  = fma2(ppB, v0.y, ob[1]);
                oa[2]  = fma2(ppA, v1.x, oa[2]);   ob[2]  = fma2(ppB, v1.x, ob[2]);
                oa[3]  = fma2(ppA, v1.y, oa[3]);   ob[3]  = fma2(ppB, v1.y, ob[3]);
                oa[4]  = fma2(ppA, v2.x, oa[4]);   ob[4]  = fma2(ppB, v2.x, ob[4]);
                oa[5]  = fma2(ppA, v2.y, oa[5]);   ob[5]  = fma2(ppB, v2.y, ob[5]);
                oa[6]  = fma2(ppA, v3.x, oa[6]);   ob[6]  = fma2(ppB, v3.x, ob[6]);
                oa[7]  = fma2(ppA, v3.y, oa[7]);   ob[7]  = fma2(ppB, v3.y, ob[7]);
                oa[8]  = fma2(ppA, v4.x, oa[8]);   ob[8]  = fma2(ppB, v4.x, ob[8]);
                oa[9]  = fma2(ppA, v4.y, oa[9]);   ob[9]  = fma2(ppB, v4.y, ob[9]);
                oa[10] = fma2(ppA, v5.x, oa[10]);  ob[10] = fma2(ppB, v5.x, ob[10]);
                oa[11] = fma2(ppA, v5.y, oa[11]);  ob[11] = fma2(ppB, v5.y, ob[11]);
            }
        }
        float invA = 1.0f / (la0 + la1);
        float invB = 1.0f / (lb0 + lb1);
        float* opA = g_o + head * HD * VOX + voxA;
        float* opB = g_o + head * HD * VOX + voxB;
#pragma unroll
        for (int d = 0; d < 12; d++) {
            float2 va = unpack2(oa[d]);
            float2 vb2 = unpack2(ob[d]);
            opA[(2 * d) * VOX]     = va.x * invA;
            opA[(2 * d + 1) * VOX] = va.y * invA;
            opB[(2 * d) * VOX]     = vb2.x * invB;
            opB[(2 * d + 1) * VOX] = vb2.y * invB;
        }
    }
}

// ---------------------------------------------------------------------------
// kernel_launch
// inputs: 0:q_in 1:k_in 2:v_in 3:Wq 4:bq 5:Wk 6:bk 7:Wv 8:bv 9:Wp 10:bp
//         11:rel_table 12:use_shift
// ---------------------------------------------------------------------------
extern "C" void kernel_launch(void* const* d_in, const int* in_sizes, int n_in,
                              void* d_out, int out_size)
{
    const float* q_in = (const float*)d_in[0];
    const float* k_in = (const float*)d_in[1];
    const float* v_in = (const float*)d_in[2];
    const float* Wq   = (const float*)d_in[3];
    const float* bq   = (const float*)d_in[4];
    const float* Wk   = (const float*)d_in[5];
    const float* bk   = (const float*)d_in[6];
    const float* Wv   = (const float*)d_in[7];
    const float* bv   = (const float*)d_in[8];
    const float* Wp   = (const float*)d_in[9];
    const float* bp   = (const float*)d_in[10];
    const float* rel  = (const float*)d_in[11];
    const int*   ush  = (const int*)d_in[12];

    float *pq, *pk, *pv, *po;
    cudaGetSymbolAddress((void**)&pq, g_q);
    cudaGetSymbolAddress((void**)&pk, g_k);
    cudaGetSymbolAddress((void**)&pv, g_v);
    cudaGetSymbolAddress((void**)&po, g_o);

    const int SMEM_GEMM = (96 * XS_STRIDE + 96 * WS_STRIDE) * (int)sizeof(float); // 90624
    cudaFuncSetAttribute(gemm_mma, cudaFuncAttributeMaxDynamicSharedMemorySize, SMEM_GEMM);

    const float scale_q = (1.0f / 4.898979485566356f) * LOG2E;  // 24^-0.5 * log2(e)

    bias_prep<<<NTOK, NTOK>>>(rel);
    gemm_mma<<<VOX / 128, 384, SMEM_GEMM>>>(q_in, Wq, bq, pq, scale_q);
    gemm_mma<<<VOX / 128, 384, SMEM_GEMM>>>(k_in, Wk, bk, pk, 1.0f);
    gemm_mma<<<VOX / 128, 384, SMEM_GEMM>>>(v_in, Wv, bv, pv, 1.0f);
    attn_kernel<<<NWIN * NH, 128>>>(ush);
    gemm_mma<<<VOX / 128, 384, SMEM_GEMM>>>(po, Wp, bp, (float*)d_out, 1.0f);
}

// round 17
// speedup vs baseline: 1.4860x; 1.1666x over previous
#include <cuda_runtime.h>
#include <cstdint>

// ---------------------------------------------------------------------------
// CrossWindowAttention3D: 3D shifted-window attention (Video-Swin style)
//   spatial 48^3, C=96, heads=4 (hd=24), window 6^3 (216 tokens), shift 3
// Round 16: tensor-core attention, fixed. The round-15 failure was a missing
//   `jb` offset in the P*V V-fragment loads (every block used block-0's V).
//   This round: fix that; revert gemm_mma to the validated round-14
//   channel-major version; gather Q/K/V channel-major in attn staging; read
//   bias straight from L2 (no smem stage) -> 93 KB smem -> 2 CTAs/SM.
// ---------------------------------------------------------------------------

#define VOX   110592            // 48*48*48
#define NC    96
#define NH    4
#define HD    24
#define NTOK  216               // 6*6*6
#define NWIN  512               // 8*8*8
#define LOG2E 1.4426950408889634f
#define MASKC (-100.0f * LOG2E)
#define XS_STRIDE 136           // gemm xs row stride
#define WS_STRIDE 100           // gemm ws row stride

// attention smem strides (floats) — all fragment accesses bank-bijective
#define QSTR 28                 // qs/ps row stride
#define KSTR 232                // ks row stride
#define VSTR 24                 // vs row stride
#define AT_T 224                // attention threads (7 warps)
// smem float offsets
#define OFF_QS 0                // [224][28] = 6272
#define OFF_KS 6272             // [24][232] = 5568
#define OFF_VS 11840            // [216][24] = 5184
#define OFF_PS 17024            // [224][28] = 6272
#define SM_FLOATS 23296         // 93184 bytes -> 2 CTAs/SM

// Scratch (device globals: allocation-free rule). All channel-major [96][VOX].
__device__ float g_q[NC * VOX];
__device__ float g_k[NC * VOX];
__device__ float g_v[NC * VOX];
__device__ float g_o[NC * VOX];
__device__ float g_biasT[NH * NTOK * NTOK];   // [head][key j][query i], *log2(e)

__device__ __forceinline__ float ex2f(float x) {
    float r;
    asm("ex2.approx.ftz.f32 %0, %1;" : "=f"(r) : "f"(x));
    return r;
}
__device__ __forceinline__ uint32_t f2tf32(float f) {
    uint32_t u;
    asm("cvt.rna.tf32.f32 %0, %1;" : "=r"(u) : "f"(f));
    return u;
}
__device__ __forceinline__ uint4 cvt4(float4 v) {
    uint4 t;
    t.x = f2tf32(v.x); t.y = f2tf32(v.y); t.z = f2tf32(v.z); t.w = f2tf32(v.w);
    return t;
}
// mma.sync m16n8k8 tf32: C += A*B (fp32 accum)
__device__ __forceinline__ void mma_tf32(float c[4],
                                         const uint32_t a[4], const uint32_t b[2]) {
    asm volatile(
        "mma.sync.aligned.m16n8k8.row.col.f32.tf32.tf32.f32 "
        "{%0,%1,%2,%3}, {%4,%5,%6,%7}, {%8,%9}, {%0,%1,%2,%3};"
        : "+f"(c[0]), "+f"(c[1]), "+f"(c[2]), "+f"(c[3])
        : "r"(a[0]), "r"(a[1]), "r"(a[2]), "r"(a[3]), "r"(b[0]), "r"(b[1]));
}

// ---------------------------------------------------------------------------
// Relative-position bias table, transposed to [h][j][i], premultiplied log2e.
// ---------------------------------------------------------------------------
extern "C" __global__ void bias_prep(const float* __restrict__ rel_table)
{
    int j = blockIdx.x;      // key token
    int i = threadIdx.x;     // query token
    int iz = i / 36, iy = (i / 6) % 6, ix = i % 6;
    int jz = j / 36, jy = (j / 6) % 6, jx = j % 6;
    int idx = ((iz - jz + 5) * 11 + (iy - jy + 5)) * 11 + (ix - jx + 5);
#pragma unroll
    for (int h = 0; h < NH; h++)
        g_biasT[h * (NTOK * NTOK) + j * NTOK + i] = rel_table[idx * NH + h] * LOG2E;
}

// ---------------------------------------------------------------------------
// Projection GEMM (TF32 mma.sync), round-14 validated version (channel-major):
//   Y[96][VOX] = (W[96x96] @ X[96][VOX] + bias) * outScale
// ---------------------------------------------------------------------------
extern "C" __global__ void __launch_bounds__(384, 2)
gemm_mma(const float* __restrict__ X, const float* __restrict__ Wm,
         const float* __restrict__ bias, float* __restrict__ Y, float outScale)
{
    extern __shared__ float smem[];
    float* xs = smem;                    // [96][XS_STRIDE] tf32 bits
    float* ws = smem + 96 * XS_STRIDE;   // [96][WS_STRIDE] tf32 bits

    const int tid   = threadIdx.x;
    const int vbase = blockIdx.x * 128;

    for (int i = tid; i < 96 * 32; i += 384) {
        int row = i >> 5;
        int c4  = i & 31;
        float4 v = reinterpret_cast<const float4*>(X + row * VOX + vbase)[c4];
        *reinterpret_cast<uint4*>(&xs[row * XS_STRIDE + c4 * 4]) = cvt4(v);
    }
    for (int i = tid; i < 96 * 24; i += 384) {
        int co = i / 24;
        int c4 = i - co * 24;
        float4 v = reinterpret_cast<const float4*>(Wm + co * 96)[c4];
        *reinterpret_cast<uint4*>(&ws[co * WS_STRIDE + c4 * 4]) = cvt4(v);
    }
    __syncthreads();

    const int warp = tid >> 5;
    const int lane = tid & 31;
    const int gid  = lane >> 2;
    const int tig  = lane & 3;
    const int m0   = (warp % 3) * 32;
    const int n0   = (warp / 3) * 32;

    const uint32_t* xsu = reinterpret_cast<const uint32_t*>(xs);
    const uint32_t* wsu = reinterpret_cast<const uint32_t*>(ws);

    float cf[2][4][4];
#pragma unroll
    for (int mf = 0; mf < 2; mf++)
#pragma unroll
        for (int nf = 0; nf < 4; nf++)
#pragma unroll
            for (int e = 0; e < 4; e++) cf[mf][nf][e] = 0.f;

#pragma unroll
    for (int ks = 0; ks < 12; ks++) {
        const int k0 = ks * 8;
        uint32_t a[2][4];
#pragma unroll
        for (int mf = 0; mf < 2; mf++) {
            int r = (m0 + mf * 16 + gid) * WS_STRIDE + k0 + tig;
            a[mf][0] = wsu[r];
            a[mf][1] = wsu[r + 8 * WS_STRIDE];
            a[mf][2] = wsu[r + 4];
            a[mf][3] = wsu[r + 8 * WS_STRIDE + 4];
        }
        uint32_t b[4][2];
#pragma unroll
        for (int nf = 0; nf < 4; nf++) {
            int c = (k0 + tig) * XS_STRIDE + n0 + nf * 8 + gid;
            b[nf][0] = xsu[c];
            b[nf][1] = xsu[c + 4 * XS_STRIDE];
        }
#pragma unroll
        for (int mf = 0; mf < 2; mf++)
#pragma unroll
            for (int nf = 0; nf < 4; nf++)
                mma_tf32(cf[mf][nf], a[mf], b[nf]);
    }

#pragma unroll
    for (int mf = 0; mf < 2; mf++) {
        int r0 = m0 + mf * 16 + gid;
        int r1 = r0 + 8;
        float bb0 = bias[r0];
        float bb1 = bias[r1];
#pragma unroll
        for (int nf = 0; nf < 4; nf++) {
            int c = vbase + n0 + nf * 8 + 2 * tig;
            float2 s0 = make_float2((cf[mf][nf][0] + bb0) * outScale,
                                    (cf[mf][nf][1] + bb0) * outScale);
            float2 s1 = make_float2((cf[mf][nf][2] + bb1) * outScale,
                                    (cf[mf][nf][3] + bb1) * outScale);
            *reinterpret_cast<float2*>(&Y[r0 * VOX + c]) = s0;
            *reinterpret_cast<float2*>(&Y[r1 * VOX + c]) = s1;
        }
    }
}

// ---------------------------------------------------------------------------
// Tensor-core attention: one CTA per (window, head), 7 warps, 2 CTAs/SM.
// Warp w owns query rows [32w, 32w+32) (rows 216-223 dummy, zero-Q, output
// suppressed). Keys in 9 blocks of 24: QK mma -> bias(from L2)+mask+exp2 on
// C-frags (tf32-rounded P, consistent row-sums in regs) -> P to smem -> AV
// mma accumulate (V indexed GLOBALLY: jb + local — the round-15 fix).
// ---------------------------------------------------------------------------
extern "C" __global__ void __launch_bounds__(AT_T, 2)
attn_mma(const int* __restrict__ use_shift)
{
    extern __shared__ float sm[];
    float* qs = sm + OFF_QS;
    float* ks = sm + OFF_KS;
    float* vs = sm + OFF_VS;
    float* ps = sm + OFF_PS;
    __shared__ int voxof[NTOK];
    __shared__ int rcode[NTOK];

    const int win  = blockIdx.x >> 2;
    const int head = blockIdx.x & 3;
    const int tid  = threadIdx.x;
    const bool sh  = (use_shift[0] != 0);
    const int shift = sh ? 3 : 0;
    const int wx = win & 7, wy = (win >> 3) & 7, wz = win >> 6;
    const bool needmask = sh && (wx == 7 || wy == 7 || wz == 7);

    if (tid < NTOK) {
        int t = tid;
        int tz = t / 36, ty = (t / 6) % 6, tx = t % 6;
        int gz = wz * 6 + tz, gy = wy * 6 + ty, gx = wx * 6 + tx;
        int sz = gz + shift; if (sz >= 48) sz -= 48;
        int sy = gy + shift; if (sy >= 48) sy -= 48;
        int sx = gx + shift; if (sx >= 48) sx -= 48;
        voxof[t] = (sz * 48 + sy) * 48 + sx;
        int rz = gz < 42 ? 0 : (gz < 45 ? 1 : 2);
        int ry = gy < 42 ? 0 : (gy < 45 ? 1 : 2);
        int rx = gx < 42 ? 0 : (gx < 45 ? 1 : 2);
        rcode[t] = rz * 9 + ry * 3 + rx;
    }
    __syncthreads();

    // Stage Q,K,V from channel-major gmem (24B token runs, R10 pattern),
    // converting to tf32. qs/vs token-major; ks dim-major (transposed).
    const int chb = head * HD;
    const float* qb = g_q + chb * VOX;
    const float* kb = g_k + chb * VOX;
    const float* vb = g_v + chb * VOX;
    for (int idx = tid; idx < NTOK * HD; idx += AT_T) {
        int dch = idx / NTOK;
        int j   = idx - dch * NTOK;
        int vx  = voxof[j];
        qs[j * QSTR + dch]   = __uint_as_float(f2tf32(qb[dch * VOX + vx]));
        ks[dch * KSTR + j]   = __uint_as_float(f2tf32(kb[dch * VOX + vx]));
        vs[j * VSTR + dch]   = __uint_as_float(f2tf32(vb[dch * VOX + vx]));
    }
    // zero dummy q rows 216-223
    for (int i = tid; i < 8 * QSTR; i += AT_T) qs[NTOK * QSTR + i] = 0.f;
    __syncthreads();

    const int warp = tid >> 5;       // 0..6
    const int lane = tid & 31;
    const int gid  = lane >> 2;
    const int tig  = lane & 3;
    const int m0   = warp * 32;

    const uint32_t* qsu = reinterpret_cast<const uint32_t*>(qs);
    const uint32_t* ksu = reinterpret_cast<const uint32_t*>(ks);
    const uint32_t* vsu = reinterpret_cast<const uint32_t*>(vs);
    const uint32_t* psu = reinterpret_cast<const uint32_t*>(ps);

    // Q fragments (persist across all key blocks)
    uint32_t qf[2][3][4];
#pragma unroll
    for (int mf = 0; mf < 2; mf++) {
        int r = (m0 + mf * 16 + gid) * QSTR;
#pragma unroll
        for (int kx = 0; kx < 3; kx++) {
            int kk = kx * 8 + tig;
            qf[mf][kx][0] = qsu[r + kk];
            qf[mf][kx][1] = qsu[r + 8 * QSTR + kk];
            qf[mf][kx][2] = qsu[r + kk + 4];
            qf[mf][kx][3] = qsu[r + 8 * QSTR + kk + 4];
        }
    }

    int i0[2], i1c[2], rc0[2], rc1[2], vx0[2], vx1[2];
    bool v1ok[2];
#pragma unroll
    for (int mf = 0; mf < 2; mf++) {
        i0[mf]  = m0 + mf * 16 + gid;          // always < 216
        int i1  = i0[mf] + 8;
        v1ok[mf] = (i1 < NTOK);
        i1c[mf] = v1ok[mf] ? i1 : (NTOK - 1);
        rc0[mf] = rcode[i0[mf]];
        rc1[mf] = rcode[i1c[mf]];
        vx0[mf] = voxof[i0[mf]];
        vx1[mf] = voxof[i1c[mf]];
    }

    const float* __restrict__ biasHead = g_biasT + head * (NTOK * NTOK);

    float ofr[2][3][4];
    float lsum[2][2];
#pragma unroll
    for (int mf = 0; mf < 2; mf++) {
        lsum[mf][0] = 0.f; lsum[mf][1] = 0.f;
#pragma unroll
        for (int nf = 0; nf < 3; nf++)
#pragma unroll
            for (int e = 0; e < 4; e++) ofr[mf][nf][e] = 0.f;
    }

    for (int blk = 0; blk < 9; blk++) {
        const int jb = blk * 24;

        // QK^T
        float sf[2][3][4];
#pragma unroll
        for (int mf = 0; mf < 2; mf++)
#pragma unroll
            for (int nf = 0; nf < 3; nf++)
#pragma unroll
                for (int e = 0; e < 4; e++) sf[mf][nf][e] = 0.f;
#pragma unroll
        for (int kx = 0; kx < 3; kx++) {
#pragma unroll
            for (int nf = 0; nf < 3; nf++) {
                uint32_t b[2];
                int col = jb + nf * 8 + gid;
                b[0] = ksu[(kx * 8 + tig) * KSTR + col];
                b[1] = ksu[(kx * 8 + tig + 4) * KSTR + col];
                mma_tf32(sf[0][nf], qf[0][kx], b);
                mma_tf32(sf[1][nf], qf[1][kx], b);
            }
        }
        __syncthreads();   // all warps done reading prev block's P

        // softmax on fragments (bias from L2) -> tf32 P to smem
#pragma unroll
        for (int mf = 0; mf < 2; mf++) {
#pragma unroll
            for (int nf = 0; nf < 3; nf++) {
                int jj0 = nf * 8 + 2 * tig;
                int jj1 = jj0 + 1;
                float s0 = sf[mf][nf][0] + biasHead[(jb + jj0) * NTOK + i0[mf]];
                float s1 = sf[mf][nf][1] + biasHead[(jb + jj1) * NTOK + i0[mf]];
                float s2 = sf[mf][nf][2] + biasHead[(jb + jj0) * NTOK + i1c[mf]];
                float s3 = sf[mf][nf][3] + biasHead[(jb + jj1) * NTOK + i1c[mf]];
                if (needmask) {
                    int rj0 = rcode[jb + jj0];
                    int rj1 = rcode[jb + jj1];
                    if (rj0 != rc0[mf]) s0 += MASKC;
                    if (rj1 != rc0[mf]) s1 += MASKC;
                    if (rj0 != rc1[mf]) s2 += MASKC;
                    if (rj1 != rc1[mf]) s3 += MASKC;
                }
                float p0 = __uint_as_float(f2tf32(ex2f(s0)));
                float p1 = __uint_as_float(f2tf32(ex2f(s1)));
                float p2 = __uint_as_float(f2tf32(ex2f(s2)));
                float p3 = __uint_as_float(f2tf32(ex2f(s3)));
                lsum[mf][0] += p0 + p1;
                lsum[mf][1] += p2 + p3;
                int r0 = i0[mf] * QSTR + jj0;
                int r1 = (i0[mf] + 8) * QSTR + jj0;   // dummy rows exist in ps
                *reinterpret_cast<float2*>(&ps[r0]) = make_float2(p0, p1);
                *reinterpret_cast<float2*>(&ps[r1]) = make_float2(p2, p3);
            }
        }
        __syncthreads();   // P visible

        // P * V accumulate — V indexed GLOBALLY (jb + local): the R15 fix.
#pragma unroll
        for (int kx = 0; kx < 3; kx++) {
            uint32_t a[2][4];
#pragma unroll
            for (int mf = 0; mf < 2; mf++) {
                int r = (m0 + mf * 16 + gid) * QSTR + kx * 8 + tig;
                a[mf][0] = psu[r];
                a[mf][1] = psu[r + 8 * QSTR];
                a[mf][2] = psu[r + 4];
                a[mf][3] = psu[r + 8 * QSTR + 4];
            }
#pragma unroll
            for (int nf = 0; nf < 3; nf++) {
                uint32_t b[2];
                b[0] = vsu[(jb + kx * 8 + tig) * VSTR + nf * 8 + gid];
                b[1] = vsu[(jb + kx * 8 + tig + 4) * VSTR + nf * 8 + gid];
                mma_tf32(ofr[0][nf], a[0], b);
                mma_tf32(ofr[1][nf], a[1], b);
            }
        }
    }

    // row-sum reduce across the 4 tig lanes (quad shares rows)
#pragma unroll
    for (int mf = 0; mf < 2; mf++) {
#pragma unroll
        for (int h = 0; h < 2; h++) {
            float l = lsum[mf][h];
            l += __shfl_xor_sync(0xFFFFFFFFu, l, 1);
            l += __shfl_xor_sync(0xFFFFFFFFu, l, 2);
            lsum[mf][h] = 1.0f / l;
        }
    }

    // store O channel-major (g_o[ch][vox]; ch = head*24 + d)
#pragma unroll
    for (int mf = 0; mf < 2; mf++) {
        float inv0 = lsum[mf][0];
        float inv1 = lsum[mf][1];
#pragma unroll
        for (int nf = 0; nf < 3; nf++) {
            int d0 = nf * 8 + 2 * tig;
            int d1 = d0 + 1;
            g_o[(chb + d0) * VOX + vx0[mf]] = ofr[mf][nf][0] * inv0;
            g_o[(chb + d1) * VOX + vx0[mf]] = ofr[mf][nf][1] * inv0;
            if (v1ok[mf]) {
                g_o[(chb + d0) * VOX + vx1[mf]] = ofr[mf][nf][2] * inv1;
                g_o[(chb + d1) * VOX + vx1[mf]] = ofr[mf][nf][3] * inv1;
            }
        }
    }
}

// ---------------------------------------------------------------------------
// kernel_launch
// inputs: 0:q_in 1:k_in 2:v_in 3:Wq 4:bq 5:Wk 6:bk 7:Wv 8:bv 9:Wp 10:bp
//         11:rel_table 12:use_shift
// ---------------------------------------------------------------------------
extern "C" void kernel_launch(void* const* d_in, const int* in_sizes, int n_in,
                              void* d_out, int out_size)
{
    const float* q_in = (const float*)d_in[0];
    const float* k_in = (const float*)d_in[1];
    const float* v_in = (const float*)d_in[2];
    const float* Wq   = (const float*)d_in[3];
    const float* bq   = (const float*)d_in[4];
    const float* Wk   = (const float*)d_in[5];
    const float* bk   = (const float*)d_in[6];
    const float* Wv   = (const float*)d_in[7];
    const float* bv   = (const float*)d_in[8];
    const float* Wp   = (const float*)d_in[9];
    const float* bp   = (const float*)d_in[10];
    const float* rel  = (const float*)d_in[11];
    const int*   ush  = (const int*)d_in[12];

    float *pq, *pk, *pv, *po;
    cudaGetSymbolAddress((void**)&pq, g_q);
    cudaGetSymbolAddress((void**)&pk, g_k);
    cudaGetSymbolAddress((void**)&pv, g_v);
    cudaGetSymbolAddress((void**)&po, g_o);

    const int SMEM_GEMM = (96 * XS_STRIDE + 96 * WS_STRIDE) * (int)sizeof(float); // 90624
    cudaFuncSetAttribute(gemm_mma, cudaFuncAttributeMaxDynamicSharedMemorySize, SMEM_GEMM);
    const int SMEM_ATTN = SM_FLOATS * (int)sizeof(float);                          // 93184
    cudaFuncSetAttribute(attn_mma, cudaFuncAttributeMaxDynamicSharedMemorySize, SMEM_ATTN);

    const float scale_q = (1.0f / 4.898979485566356f) * LOG2E;  // 24^-0.5 * log2(e)

    bias_prep<<<NTOK, NTOK>>>(rel);
    gemm_mma<<<VOX / 128, 384, SMEM_GEMM>>>(q_in, Wq, bq, pq, scale_q);
    gemm_mma<<<VOX / 128, 384, SMEM_GEMM>>>(k_in, Wk, bk, pk, 1.0f);
    gemm_mma<<<VOX / 128, 384, SMEM_GEMM>>>(v_in, Wv, bv, pv, 1.0f);
    attn_mma<<<NWIN * NH, AT_T, SMEM_ATTN>>>(ush);
    gemm_mma<<<VOX / 128, 384, SMEM_GEMM>>>(po, Wp, bp, (float*)d_out, 1.0f);
}